// round 13
// baseline (speedup 1.0000x reference)
#include <cuda_runtime.h>
#include <cuda_fp16.h>
#include <cstdint>

#define TOKENS 8192
#define HIDDEN 1024
#define INTER  2816
#define NEXP   8
#define NSLOTS (2*TOKENS)
#define MAX_TILES 160
#define BM 128
#define NW4 ((NEXP * INTER * HIDDEN) / 4)
#define ROUTE_BLOCKS (TOKENS / 8)
#define CVT_BLOCKS ((3 * NW4) / 2048)   // 8448 exactly
#define N_GU_BLK (INTER / 64)           // 44
#define N_DN_BLK (HIDDEN / 128)         // 8
#define PERSIST_CTAS 296                // 2 per SM x 148

// ---------------- device scratch ----------------
__device__ int   g_cnt[NEXP];
__device__ int   g_cur[NEXP];
__device__ int   g_off[NEXP + 1];
__device__ int   g_e0[TOKENS];
__device__ int   g_e1[TOKENS];
__device__ float g_w0[TOKENS];
__device__ float g_w1[TOKENS];
__device__ int   g_row_token[NSLOTS];
__device__ float g_row_w[NSLOTS];
__device__ int   g_tile_e[MAX_TILES];
__device__ int   g_tile_m0[MAX_TILES];
__device__ int   g_tile_rows[MAX_TILES];
__device__ int   g_ntiles;
__device__ int   g_sync[2 + MAX_TILES]; // [0]=q1 [1]=q2 [2..]=m-tile ready counts

__device__ __half g_xh  [(size_t)TOKENS * HIDDEN];
__device__ __half g_wgph[(size_t)NEXP * INTER * HIDDEN];
__device__ __half g_wuph[(size_t)NEXP * INTER * HIDDEN];
__device__ __half g_wdph[(size_t)NEXP * HIDDEN * INTER];
__device__ __half g_act [(size_t)NSLOTS * INTER];

// ---------------- helpers ----------------
__device__ __forceinline__ uint32_t smem_u32(const void* p) {
    uint32_t a;
    asm("{ .reg .u64 t; cvta.to.shared.u64 t, %1; cvt.u32.u64 %0, t; }" : "=r"(a) : "l"(p));
    return a;
}
__device__ __forceinline__ void cp16(uint32_t dst, const void* src, int src_sz) {
    asm volatile("cp.async.cg.shared.global [%0], [%1], 16, %2;\n"
                 :: "r"(dst), "l"(src), "r"(src_sz) : "memory");
}
__device__ __forceinline__ void cp_commit() {
    asm volatile("cp.async.commit_group;\n" ::: "memory");
}
__device__ __forceinline__ void cp_wait2() {
    asm volatile("cp.async.wait_group 2;\n" ::: "memory");
}
__device__ __forceinline__ void mma_f16(float* c, const uint32_t* a, const uint32_t* b) {
    asm volatile(
        "mma.sync.aligned.m16n8k16.row.col.f32.f16.f16.f32 "
        "{%0,%1,%2,%3},{%4,%5,%6,%7},{%8,%9},{%0,%1,%2,%3};"
        : "+f"(c[0]), "+f"(c[1]), "+f"(c[2]), "+f"(c[3])
        : "r"(a[0]), "r"(a[1]), "r"(a[2]), "r"(a[3]), "r"(b[0]), "r"(b[1]));
}
__device__ __forceinline__ void ldsm_x4(uint32_t* r, uint32_t addr) {
    asm volatile("ldmatrix.sync.aligned.m8n8.x4.shared.b16 {%0,%1,%2,%3}, [%4];"
                 : "=r"(r[0]), "=r"(r[1]), "=r"(r[2]), "=r"(r[3]) : "r"(addr));
}
__device__ __forceinline__ void red_add_v2(float* addr, float a, float b) {
    asm volatile("red.global.add.v2.f32 [%0], {%1, %2};"
                 :: "l"(addr), "f"(a), "f"(b) : "memory");
}

// ---------------- fused routing + weight conversion ----------------
__global__ void k_routecvt(const float* __restrict__ x, const float* __restrict__ wg,
                           const float* __restrict__ wgp, const float* __restrict__ wup,
                           const float* __restrict__ wdp) {
    int tid = threadIdx.x;
    if (blockIdx.x < ROUTE_BLOCKS) {
        __shared__ float s_wg[NEXP * HIDDEN];
        for (int i = tid * 4; i < NEXP * HIDDEN; i += blockDim.x * 4)
            *(float4*)&s_wg[i] = *(const float4*)&wg[i];
        __syncthreads();
        int warp = tid >> 5, lane = tid & 31;
        int t = blockIdx.x * 8 + warp;
        float p[NEXP];
#pragma unroll
        for (int e = 0; e < NEXP; e++) p[e] = 0.f;
        const float* xr = x + (size_t)t * HIDDEN;
        __half* xh = g_xh + (size_t)t * HIDDEN;
        for (int k = lane; k < HIDDEN; k += 32) {
            float xv = xr[k];
            xh[k] = __float2half_rn(xv);
#pragma unroll
            for (int e = 0; e < NEXP; e++) p[e] += xv * s_wg[e * HIDDEN + k];
        }
#pragma unroll
        for (int e = 0; e < NEXP; e++)
#pragma unroll
            for (int o = 16; o; o >>= 1) p[e] += __shfl_xor_sync(0xffffffffu, p[e], o);
        if (lane == 0) {
            int e0 = 0;
#pragma unroll
            for (int e = 1; e < NEXP; e++) if (p[e] > p[e0]) e0 = e;
            int e1 = -1; float v1 = -1e30f;
#pragma unroll
            for (int e = 0; e < NEXP; e++) {
                if (e == e0) continue;
                if (e1 < 0 || p[e] > v1) { e1 = e; v1 = p[e]; }
            }
            float b = __expf(v1 - p[e0]);
            float inv = 1.f / (1.f + b);
            g_e0[t] = e0; g_e1[t] = e1;
            g_w0[t] = inv; g_w1[t] = b * inv;
            atomicAdd(&g_cnt[e0], 1);
            atomicAdd(&g_cnt[e1], 1);
        }
    } else {
        long long base = (long long)(blockIdx.x - ROUTE_BLOCKS) * 2048 + tid;
#pragma unroll
        for (int it = 0; it < 8; it++) {
            long long i = base + (long long)it * 256;
            const float* src; __half* dst; long long j;
            if (i < NW4)            { src = wgp; dst = g_wgph; j = i; }
            else if (i < 2LL*NW4)   { src = wup; dst = g_wuph; j = i - NW4; }
            else if (i < 3LL*NW4)   { src = wdp; dst = g_wdph; j = i - 2LL*NW4; }
            else continue;
            float4 v = ((const float4*)src)[j];
            __half2 h01 = __floats2half2_rn(v.x, v.y);
            __half2 h23 = __floats2half2_rn(v.z, v.w);
            uint2 o;
            o.x = *(uint32_t*)&h01;
            o.y = *(uint32_t*)&h23;
            ((uint2*)dst)[j] = o;
        }
    }
}

__global__ void k_plan() {
    if (threadIdx.x == 0) {
        int off = 0, nt = 0;
        for (int e = 0; e < NEXP; e++) {
            g_off[e] = off;
            int c = g_cnt[e];
            int m0 = 0;
            while (m0 < c) {
                g_tile_e[nt] = e;
                g_tile_m0[nt] = off + m0;
                g_tile_rows[nt] = min(BM, c - m0);
                m0 += BM; nt++;
            }
            off += c;
            g_cur[e] = 0;
        }
        g_off[NEXP] = off;
        g_ntiles = nt;
    }
}

__global__ void k_scatter() {
    int t = blockIdx.x * blockDim.x + threadIdx.x;
    if (t >= TOKENS) return;
    int e0 = g_e0[t], e1 = g_e1[t];
    int i0 = g_off[e0] + atomicAdd(&g_cur[e0], 1);
    g_row_token[i0] = t; g_row_w[i0] = g_w0[t];
    int i1 = g_off[e1] + atomicAdd(&g_cur[e1], 1);
    g_row_token[i1] = t; g_row_w[i1] = g_w1[t];
}

// ---------------- device tile bodies (exact R12 math) ----------------
__device__ __forceinline__ void gateup_tile(uint32_t* dsm, uint32_t sbase,
                                            int bt, int n0) {
    int e = g_tile_e[bt], m0 = g_tile_m0[bt], rows = g_tile_rows[bt];
    int tid = threadIdx.x, warp = tid >> 5, lane = tid & 31;
    int wm = warp & 3, wn = warp >> 2;

    const __half* wg_e = g_wgph + (size_t)e * INTER * HIDDEN;
    const __half* wu_e = g_wuph + (size_t)e * INTER * HIDDEN;

    const __half* a_src[4]; int a_sz[4]; uint32_t a_off[4];
#pragma unroll
    for (int i = 0; i < 4; i++) {
        int c = tid + 256 * i;
        int r = c >> 3, c8 = c & 7;
        bool v = r < rows;
        int tok = v ? g_row_token[m0 + r] : 0;
        a_src[i] = g_xh + (size_t)tok * HIDDEN + c8 * 8;
        a_sz[i] = v ? 16 : 0;
        a_off[i] = (uint32_t)(r * 128 + ((c8 ^ (r & 7)) << 4));
    }
    const __half* bg_src[2]; const __half* bu_src[2]; uint32_t b_off[2];
#pragma unroll
    for (int i = 0; i < 2; i++) {
        int c = tid + 256 * i;
        int r = c >> 3, c8 = c & 7;
        bg_src[i] = wg_e + (size_t)(n0 + r) * HIDDEN + c8 * 8;
        bu_src[i] = wu_e + (size_t)(n0 + r) * HIDDEN + c8 * 8;
        b_off[i] = (uint32_t)(r * 128 + ((c8 ^ (r & 7)) << 4));
    }

    int lr = lane & 7, grp = lane >> 3;
    int rsel = (grp & 1) << 3;
    int khalf = grp >> 1;
    uint32_t a_row[2], b_row[2];
#pragma unroll
    for (int mi = 0; mi < 2; mi++)
        a_row[mi] = (uint32_t)((wm * 32 + mi * 16 + rsel + lr) * 128);
#pragma unroll
    for (int pi = 0; pi < 2; pi++)
        b_row[pi] = (uint32_t)((wn * 32 + pi * 16 + rsel + lr) * 128);

    float accG[2][4][4], accU[2][4][4];
#pragma unroll
    for (int a = 0; a < 2; a++)
#pragma unroll
        for (int b = 0; b < 4; b++)
#pragma unroll
            for (int q = 0; q < 4; q++) { accG[a][b][q] = 0.f; accU[a][b][q] = 0.f; }

    auto load_stage = [&](int kt, int buf) {
        uint32_t base = sbase + (uint32_t)buf * 32768u;
#pragma unroll
        for (int i = 0; i < 4; i++)
            cp16(base + a_off[i], a_src[i] + kt * 64, a_sz[i]);
#pragma unroll
        for (int i = 0; i < 2; i++) {
            cp16(base + 16384u + b_off[i], bg_src[i] + kt * 64, 16);
            cp16(base + 24576u + b_off[i], bu_src[i] + kt * 64, 16);
        }
    };

    load_stage(0, 0); cp_commit();
    load_stage(1, 1); cp_commit();
    load_stage(2, 2); cp_commit();

    const int KT = HIDDEN / 64;  // 16
    for (int kt = 0; kt < KT; kt++) {
        int buf = kt % 3;
        cp_wait2();
        __syncthreads();

        uint32_t bb = sbase + (uint32_t)buf * 32768u;
#pragma unroll
        for (int s = 0; s < 4; s++) {
            uint32_t xw = (uint32_t)((((2 * s + khalf) ^ lr) << 4));
            uint32_t af[2][4];
#pragma unroll
            for (int mi = 0; mi < 2; mi++)
                ldsm_x4(af[mi], bb + a_row[mi] + xw);

            uint32_t bgf[4][2], buf16[4][2];
#pragma unroll
            for (int pi = 0; pi < 2; pi++) {
                uint32_t t4[4];
                ldsm_x4(t4, bb + 16384u + b_row[pi] + xw);
                bgf[2*pi][0] = t4[0]; bgf[2*pi+1][0] = t4[1];
                bgf[2*pi][1] = t4[2]; bgf[2*pi+1][1] = t4[3];
                ldsm_x4(t4, bb + 24576u + b_row[pi] + xw);
                buf16[2*pi][0] = t4[0]; buf16[2*pi+1][0] = t4[1];
                buf16[2*pi][1] = t4[2]; buf16[2*pi+1][1] = t4[3];
            }
#pragma unroll
            for (int mi = 0; mi < 2; mi++)
#pragma unroll
                for (int ni = 0; ni < 4; ni++) {
                    mma_f16(accG[mi][ni], af[mi], bgf[ni]);
                    mma_f16(accU[mi][ni], af[mi], buf16[ni]);
                }
        }
        __syncthreads();
        if (kt + 3 < KT) load_stage(kt + 3, buf);
        cp_commit();
    }

#pragma unroll
    for (int mi = 0; mi < 2; mi++) {
        int r_lo = wm * 32 + mi * 16 + (lane >> 2);
#pragma unroll
        for (int half = 0; half < 2; half++) {
            int row = r_lo + half * 8;
            if (row >= rows) continue;
            __half* arow = g_act + (size_t)(m0 + row) * INTER;
#pragma unroll
            for (int ni = 0; ni < 4; ni++) {
                int coln = n0 + wn * 32 + ni * 8 + (lane & 3) * 2;
                float g0 = accG[mi][ni][half * 2 + 0];
                float g1 = accG[mi][ni][half * 2 + 1];
                float u0 = accU[mi][ni][half * 2 + 0];
                float u1 = accU[mi][ni][half * 2 + 1];
                float s0 = g0 / (1.f + __expf(-g0)) * u0;
                float s1 = g1 / (1.f + __expf(-g1)) * u1;
                __half2 h = __floats2half2_rn(s0, s1);
                *(__half2*)&arow[coln] = h;
            }
        }
    }
}

__device__ __forceinline__ void down_tile(uint32_t* dsm, uint32_t sbase,
                                          int bt, int n0, float* __restrict__ out) {
    int e = g_tile_e[bt], m0 = g_tile_m0[bt], rows = g_tile_rows[bt];
    int tid = threadIdx.x, warp = tid >> 5, lane = tid & 31;
    int wm = warp & 3, wn = warp >> 2;

    const __half* wd_e = g_wdph + (size_t)e * HIDDEN * INTER;

    const __half* a_src[4]; int a_sz[4]; uint32_t a_off[4];
    const __half* b_src[4];
#pragma unroll
    for (int i = 0; i < 4; i++) {
        int c = tid + 256 * i;
        int r = c >> 3, c8 = c & 7;
        bool v = r < rows;
        a_src[i] = g_act + (size_t)(m0 + (v ? r : 0)) * INTER + c8 * 8;
        a_sz[i] = v ? 16 : 0;
        a_off[i] = (uint32_t)(r * 128 + ((c8 ^ (r & 7)) << 4));
        b_src[i] = wd_e + (size_t)(n0 + r) * INTER + c8 * 8;
    }

    int lr = lane & 7, grp = lane >> 3;
    int rsel = (grp & 1) << 3;
    int khalf = grp >> 1;
    uint32_t a_row[2], b_row[4];
#pragma unroll
    for (int mi = 0; mi < 2; mi++)
        a_row[mi] = (uint32_t)((wm * 32 + mi * 16 + rsel + lr) * 128);
#pragma unroll
    for (int pi = 0; pi < 4; pi++)
        b_row[pi] = (uint32_t)((wn * 64 + pi * 16 + rsel + lr) * 128);

    float acc[2][8][4];
#pragma unroll
    for (int a = 0; a < 2; a++)
#pragma unroll
        for (int b = 0; b < 8; b++)
#pragma unroll
            for (int q = 0; q < 4; q++) acc[a][b][q] = 0.f;

    auto load_stage = [&](int kt, int buf) {
        uint32_t base = sbase + (uint32_t)buf * 32768u;
#pragma unroll
        for (int i = 0; i < 4; i++) {
            cp16(base + a_off[i],          a_src[i] + kt * 64, a_sz[i]);
            cp16(base + 16384u + a_off[i], b_src[i] + kt * 64, 16);
        }
    };

    load_stage(0, 0); cp_commit();
    load_stage(1, 1); cp_commit();
    load_stage(2, 2); cp_commit();

    const int KT = INTER / 64;  // 44
    for (int kt = 0; kt < KT; kt++) {
        int buf = kt % 3;
        cp_wait2();
        __syncthreads();

        uint32_t bb = sbase + (uint32_t)buf * 32768u;
#pragma unroll
        for (int s = 0; s < 4; s++) {
            uint32_t xw = (uint32_t)((((2 * s + khalf) ^ lr) << 4));
            uint32_t af[2][4];
#pragma unroll
            for (int mi = 0; mi < 2; mi++)
                ldsm_x4(af[mi], bb + a_row[mi] + xw);

            uint32_t bf[8][2];
#pragma unroll
            for (int pi = 0; pi < 4; pi++) {
                uint32_t t4[4];
                ldsm_x4(t4, bb + 16384u + b_row[pi] + xw);
                bf[2*pi][0] = t4[0]; bf[2*pi+1][0] = t4[1];
                bf[2*pi][1] = t4[2]; bf[2*pi+1][1] = t4[3];
            }
#pragma unroll
            for (int mi = 0; mi < 2; mi++)
#pragma unroll
                for (int ni = 0; ni < 8; ni++)
                    mma_f16(acc[mi][ni], af[mi], bf[ni]);
        }
        __syncthreads();
        if (kt + 3 < KT) load_stage(kt + 3, buf);
        cp_commit();
    }

#pragma unroll
    for (int mi = 0; mi < 2; mi++) {
        int r_lo = wm * 32 + mi * 16 + (lane >> 2);
#pragma unroll
        for (int half = 0; half < 2; half++) {
            int row = r_lo + half * 8;
            if (row >= rows) continue;
            int tok = g_row_token[m0 + row];
            float w = g_row_w[m0 + row];
            float* orow = out + (size_t)tok * HIDDEN;
#pragma unroll
            for (int ni = 0; ni < 8; ni++) {
                int coln = n0 + wn * 64 + ni * 8 + (lane & 3) * 2;
                red_add_v2(&orow[coln],
                           w * acc[mi][ni][half * 2 + 0],
                           w * acc[mi][ni][half * 2 + 1]);
            }
        }
    }
}

// ---------------- persistent fused MoE kernel ----------------
__global__ void __launch_bounds__(256, 2)
k_moe(float* __restrict__ out) {
    extern __shared__ uint32_t dsm[];
    uint32_t sbase = smem_u32(dsm);
    __shared__ int s_task;
    int tid = threadIdx.x;

    int ntiles = g_ntiles;
    int ngu = ntiles * N_GU_BLK;
    int ndn = ntiles * N_DN_BLK;

    // ---- phase 1: gateup tiles (dynamic queue) ----
    for (;;) {
        if (tid == 0) s_task = atomicAdd(&g_sync[0], 1);
        __syncthreads();
        int task = s_task;
        if (task >= ngu) break;
        int bt = task / N_GU_BLK;
        int n0 = (task % N_GU_BLK) * 64;
        gateup_tile(dsm, sbase, bt, n0);
        // release this tile's g_act slice
        __threadfence();
        __syncthreads();
        if (tid == 0) atomicAdd(&g_sync[2 + bt], 1);
    }

    // ---- phase 2: down tiles (dynamic queue, spin on readiness) ----
    for (;;) {
        if (tid == 0) s_task = atomicAdd(&g_sync[1], 1);
        __syncthreads();
        int task = s_task;
        if (task >= ndn) break;
        int bt = task / N_DN_BLK;
        int n0 = (task % N_DN_BLK) * 128;
        if (tid == 0) {
            while (*(volatile int*)&g_sync[2 + bt] < N_GU_BLK) { }
            __threadfence();
        }
        __syncthreads();
        down_tile(dsm, sbase, bt, n0, out);
    }
}

// ---------------- launch ----------------
extern "C" void kernel_launch(void* const* d_in, const int* in_sizes, int n_in,
                              void* d_out, int out_size) {
    const float* x   = (const float*)d_in[0];
    const float* wg  = (const float*)d_in[1];
    const float* wgp = (const float*)d_in[2];
    const float* wup = (const float*)d_in[3];
    const float* wdp = (const float*)d_in[4];
    float* out = (float*)d_out;

    const int SMEM_DYN = 3 * 32768;  // 98304 B per CTA, 2 CTAs/SM
    cudaFuncSetAttribute(k_moe, cudaFuncAttributeMaxDynamicSharedMemorySize, SMEM_DYN);

    void* cnt_addr = nullptr;
    cudaGetSymbolAddress(&cnt_addr, g_cnt);
    cudaMemsetAsync(cnt_addr, 0, NEXP * sizeof(int));
    void* sync_addr = nullptr;
    cudaGetSymbolAddress(&sync_addr, g_sync);
    cudaMemsetAsync(sync_addr, 0, (2 + MAX_TILES) * sizeof(int));

    k_routecvt<<<ROUTE_BLOCKS + CVT_BLOCKS, 256>>>(x, wg, wgp, wup, wdp);
    k_plan<<<1, 1>>>();
    k_scatter<<<TOKENS / 256, 256>>>();

    cudaMemsetAsync(d_out, 0, (size_t)TOKENS * HIDDEN * sizeof(float));

    k_moe<<<PERSIST_CTAS, 256, SMEM_DYN>>>(out);
}

// round 14
// speedup vs baseline: 1.2157x; 1.2157x over previous
#include <cuda_runtime.h>
#include <cuda_fp16.h>
#include <cstdint>

#define TOKENS 8192
#define HIDDEN 1024
#define INTER  2816
#define NEXP   8
#define NSLOTS (2*TOKENS)
#define MAX_TILES 160
#define BM 128
#define NW4 ((NEXP * INTER * HIDDEN) / 4)
#define ROUTE_BLOCKS (TOKENS / 8)
#define CVT_BLOCKS ((3 * NW4) / 2048)   // 8448 exactly

// ---------------- device scratch ----------------
__device__ int   g_cnt[NEXP];
__device__ int   g_cur[NEXP];
__device__ int   g_off[NEXP + 1];
__device__ int   g_e0[TOKENS];
__device__ int   g_e1[TOKENS];
__device__ float g_w0[TOKENS];
__device__ float g_w1[TOKENS];
__device__ int   g_row_token[NSLOTS];
__device__ float g_row_w[NSLOTS];
__device__ int   g_tile_e[MAX_TILES];
__device__ int   g_tile_m0[MAX_TILES];
__device__ int   g_tile_rows[MAX_TILES];
__device__ int   g_ntiles;

__device__ __half g_xh  [(size_t)TOKENS * HIDDEN];
__device__ __half g_wgph[(size_t)NEXP * INTER * HIDDEN];
__device__ __half g_wuph[(size_t)NEXP * INTER * HIDDEN];
__device__ __half g_wdph[(size_t)NEXP * HIDDEN * INTER];
__device__ __half g_act [(size_t)NSLOTS * INTER];

// ---------------- helpers ----------------
__device__ __forceinline__ uint32_t smem_u32(const void* p) {
    uint32_t a;
    asm("{ .reg .u64 t; cvta.to.shared.u64 t, %1; cvt.u32.u64 %0, t; }" : "=r"(a) : "l"(p));
    return a;
}
__device__ __forceinline__ void cp16(uint32_t dst, const void* src, int src_sz) {
    asm volatile("cp.async.cg.shared.global [%0], [%1], 16, %2;\n"
                 :: "r"(dst), "l"(src), "r"(src_sz) : "memory");
}
__device__ __forceinline__ void cp_commit() {
    asm volatile("cp.async.commit_group;\n" ::: "memory");
}
__device__ __forceinline__ void cp_wait2() {
    asm volatile("cp.async.wait_group 2;\n" ::: "memory");
}
__device__ __forceinline__ void mma_f16(float* c, const uint32_t* a, const uint32_t* b) {
    asm volatile(
        "mma.sync.aligned.m16n8k16.row.col.f32.f16.f16.f32 "
        "{%0,%1,%2,%3},{%4,%5,%6,%7},{%8,%9},{%0,%1,%2,%3};"
        : "+f"(c[0]), "+f"(c[1]), "+f"(c[2]), "+f"(c[3])
        : "r"(a[0]), "r"(a[1]), "r"(a[2]), "r"(a[3]), "r"(b[0]), "r"(b[1]));
}
__device__ __forceinline__ void ldsm_x4(uint32_t* r, uint32_t addr) {
    asm volatile("ldmatrix.sync.aligned.m8n8.x4.shared.b16 {%0,%1,%2,%3}, [%4];"
                 : "=r"(r[0]), "=r"(r[1]), "=r"(r[2]), "=r"(r[3]) : "r"(addr));
}
// vector fp32x2 reduction (sm_90+): one RED.64 instead of two RED.32
__device__ __forceinline__ void red_add_v2(float* addr, float a, float b) {
    asm volatile("red.global.add.v2.f32 [%0], {%1, %2};"
                 :: "l"(addr), "f"(a), "f"(b) : "memory");
}

// ---------------- fused routing + weight conversion ----------------
__global__ void k_routecvt(const float* __restrict__ x, const float* __restrict__ wg,
                           const float* __restrict__ wgp, const float* __restrict__ wup,
                           const float* __restrict__ wdp) {
    int tid = threadIdx.x;
    if (blockIdx.x < ROUTE_BLOCKS) {
        // ---- routing (also emits fp16 x) ----
        __shared__ float s_wg[NEXP * HIDDEN];
        for (int i = tid * 4; i < NEXP * HIDDEN; i += blockDim.x * 4)
            *(float4*)&s_wg[i] = *(const float4*)&wg[i];
        __syncthreads();
        int warp = tid >> 5, lane = tid & 31;
        int t = blockIdx.x * 8 + warp;
        float p[NEXP];
#pragma unroll
        for (int e = 0; e < NEXP; e++) p[e] = 0.f;
        const float* xr = x + (size_t)t * HIDDEN;
        __half* xh = g_xh + (size_t)t * HIDDEN;
        for (int k = lane; k < HIDDEN; k += 32) {
            float xv = xr[k];
            xh[k] = __float2half_rn(xv);
#pragma unroll
            for (int e = 0; e < NEXP; e++) p[e] += xv * s_wg[e * HIDDEN + k];
        }
#pragma unroll
        for (int e = 0; e < NEXP; e++)
#pragma unroll
            for (int o = 16; o; o >>= 1) p[e] += __shfl_xor_sync(0xffffffffu, p[e], o);
        if (lane == 0) {
            int e0 = 0;
#pragma unroll
            for (int e = 1; e < NEXP; e++) if (p[e] > p[e0]) e0 = e;
            int e1 = -1; float v1 = -1e30f;
#pragma unroll
            for (int e = 0; e < NEXP; e++) {
                if (e == e0) continue;
                if (e1 < 0 || p[e] > v1) { e1 = e; v1 = p[e]; }
            }
            float b = __expf(v1 - p[e0]);
            float inv = 1.f / (1.f + b);
            g_e0[t] = e0; g_e1[t] = e1;
            g_w0[t] = inv; g_w1[t] = b * inv;
            atomicAdd(&g_cnt[e0], 1);
            atomicAdd(&g_cnt[e1], 1);
        }
    } else {
        // ---- weight fp32 -> fp16 conversion, 8 float4 per thread ----
        long long base = (long long)(blockIdx.x - ROUTE_BLOCKS) * 2048 + tid;
#pragma unroll
        for (int it = 0; it < 8; it++) {
            long long i = base + (long long)it * 256;
            const float* src; __half* dst; long long j;
            if (i < NW4)            { src = wgp; dst = g_wgph; j = i; }
            else if (i < 2LL*NW4)   { src = wup; dst = g_wuph; j = i - NW4; }
            else if (i < 3LL*NW4)   { src = wdp; dst = g_wdph; j = i - 2LL*NW4; }
            else continue;
            float4 v = ((const float4*)src)[j];
            __half2 h01 = __floats2half2_rn(v.x, v.y);
            __half2 h23 = __floats2half2_rn(v.z, v.w);
            uint2 o;
            o.x = *(uint32_t*)&h01;
            o.y = *(uint32_t*)&h23;
            ((uint2*)dst)[j] = o;
        }
    }
}

__global__ void k_plan() {
    if (threadIdx.x == 0) {
        int off = 0, nt = 0;
        for (int e = 0; e < NEXP; e++) {
            g_off[e] = off;
            int c = g_cnt[e];
            int m0 = 0;
            while (m0 < c) {
                g_tile_e[nt] = e;
                g_tile_m0[nt] = off + m0;
                g_tile_rows[nt] = min(BM, c - m0);
                m0 += BM; nt++;
            }
            off += c;
            g_cur[e] = 0;
        }
        g_off[NEXP] = off;
        g_ntiles = nt;
    }
}

__global__ void k_scatter() {
    int t = blockIdx.x * blockDim.x + threadIdx.x;
    if (t >= TOKENS) return;
    int e0 = g_e0[t], e1 = g_e1[t];
    int i0 = g_off[e0] + atomicAdd(&g_cur[e0], 1);
    g_row_token[i0] = t; g_row_w[i0] = g_w0[t];
    int i1 = g_off[e1] + atomicAdd(&g_cur[e1], 1);
    g_row_token[i1] = t; g_row_w[i1] = g_w1[t];
}

// ---------------- K4: gate+up GEMM + SwiGLU ----------------
// CTA 128(tok) x 64(inter) per matrix; 256 thr, 8 warps 4m x 2n,
// warp tile 32x32 per matrix; BK=64; 3-stage ring (32KB/stage); 2 CTAs/SM.
__global__ void __launch_bounds__(256, 2)
k_gateup() {
    int bt = blockIdx.y;
    if (bt >= g_ntiles) return;
    int e = g_tile_e[bt], m0 = g_tile_m0[bt], rows = g_tile_rows[bt];
    int n0 = blockIdx.x * 64;

    extern __shared__ uint32_t dsm[];
    uint32_t sbase = smem_u32(dsm);

    int tid = threadIdx.x, warp = tid >> 5, lane = tid & 31;
    int wm = warp & 3, wn = warp >> 2;

    const __half* wg_e = g_wgph + (size_t)e * INTER * HIDDEN;
    const __half* wu_e = g_wuph + (size_t)e * INTER * HIDDEN;

    const __half* a_src[4]; int a_sz[4]; uint32_t a_off[4];
#pragma unroll
    for (int i = 0; i < 4; i++) {
        int c = tid + 256 * i;
        int r = c >> 3, c8 = c & 7;
        bool v = r < rows;
        int tok = v ? g_row_token[m0 + r] : 0;
        a_src[i] = g_xh + (size_t)tok * HIDDEN + c8 * 8;
        a_sz[i] = v ? 16 : 0;
        a_off[i] = (uint32_t)(r * 128 + ((c8 ^ (r & 7)) << 4));
    }
    const __half* bg_src[2]; const __half* bu_src[2]; uint32_t b_off[2];
#pragma unroll
    for (int i = 0; i < 2; i++) {
        int c = tid + 256 * i;
        int r = c >> 3, c8 = c & 7;
        bg_src[i] = wg_e + (size_t)(n0 + r) * HIDDEN + c8 * 8;
        bu_src[i] = wu_e + (size_t)(n0 + r) * HIDDEN + c8 * 8;
        b_off[i] = (uint32_t)(r * 128 + ((c8 ^ (r & 7)) << 4));
    }

    int lr = lane & 7, grp = lane >> 3;
    int rsel = (grp & 1) << 3;
    int khalf = grp >> 1;
    uint32_t a_row[2], b_row[2];
#pragma unroll
    for (int mi = 0; mi < 2; mi++)
        a_row[mi] = (uint32_t)((wm * 32 + mi * 16 + rsel + lr) * 128);
#pragma unroll
    for (int pi = 0; pi < 2; pi++)
        b_row[pi] = (uint32_t)((wn * 32 + pi * 16 + rsel + lr) * 128);

    float accG[2][4][4], accU[2][4][4];
#pragma unroll
    for (int a = 0; a < 2; a++)
#pragma unroll
        for (int b = 0; b < 4; b++)
#pragma unroll
            for (int q = 0; q < 4; q++) { accG[a][b][q] = 0.f; accU[a][b][q] = 0.f; }

    auto load_stage = [&](int kt, int buf) {
        uint32_t base = sbase + (uint32_t)buf * 32768u;
#pragma unroll
        for (int i = 0; i < 4; i++)
            cp16(base + a_off[i], a_src[i] + kt * 64, a_sz[i]);
#pragma unroll
        for (int i = 0; i < 2; i++) {
            cp16(base + 16384u + b_off[i], bg_src[i] + kt * 64, 16);
            cp16(base + 24576u + b_off[i], bu_src[i] + kt * 64, 16);
        }
    };

    load_stage(0, 0); cp_commit();
    load_stage(1, 1); cp_commit();
    load_stage(2, 2); cp_commit();

    const int KT = HIDDEN / 64;  // 16
    for (int kt = 0; kt < KT; kt++) {
        int buf = kt % 3;
        cp_wait2();
        __syncthreads();

        uint32_t bb = sbase + (uint32_t)buf * 32768u;
#pragma unroll
        for (int s = 0; s < 4; s++) {
            uint32_t xw = (uint32_t)((((2 * s + khalf) ^ lr) << 4));
            uint32_t af[2][4];
#pragma unroll
            for (int mi = 0; mi < 2; mi++)
                ldsm_x4(af[mi], bb + a_row[mi] + xw);

            uint32_t bgf[4][2], buf16[4][2];
#pragma unroll
            for (int pi = 0; pi < 2; pi++) {
                uint32_t t4[4];
                ldsm_x4(t4, bb + 16384u + b_row[pi] + xw);
                bgf[2*pi][0] = t4[0]; bgf[2*pi+1][0] = t4[1];
                bgf[2*pi][1] = t4[2]; bgf[2*pi+1][1] = t4[3];
                ldsm_x4(t4, bb + 24576u + b_row[pi] + xw);
                buf16[2*pi][0] = t4[0]; buf16[2*pi+1][0] = t4[1];
                buf16[2*pi][1] = t4[2]; buf16[2*pi+1][1] = t4[3];
            }
#pragma unroll
            for (int mi = 0; mi < 2; mi++)
#pragma unroll
                for (int ni = 0; ni < 4; ni++) {
                    mma_f16(accG[mi][ni], af[mi], bgf[ni]);
                    mma_f16(accU[mi][ni], af[mi], buf16[ni]);
                }
        }
        __syncthreads();
        if (kt + 3 < KT) load_stage(kt + 3, buf);
        cp_commit();
    }

    // epilogue: act = fp16(silu(g) * u), direct stores
#pragma unroll
    for (int mi = 0; mi < 2; mi++) {
        int r_lo = wm * 32 + mi * 16 + (lane >> 2);
#pragma unroll
        for (int half = 0; half < 2; half++) {
            int row = r_lo + half * 8;
            if (row >= rows) continue;
            __half* arow = g_act + (size_t)(m0 + row) * INTER;
#pragma unroll
            for (int ni = 0; ni < 4; ni++) {
                int coln = n0 + wn * 32 + ni * 8 + (lane & 3) * 2;
                float g0 = accG[mi][ni][half * 2 + 0];
                float g1 = accG[mi][ni][half * 2 + 1];
                float u0 = accU[mi][ni][half * 2 + 0];
                float u1 = accU[mi][ni][half * 2 + 1];
                float s0 = g0 / (1.f + __expf(-g0)) * u0;
                float s1 = g1 / (1.f + __expf(-g1)) * u1;
                __half2 h = __floats2half2_rn(s0, s1);
                *(__half2*)&arow[coln] = h;
            }
        }
    }
}

// ---------------- K5: down GEMM -> weighted v2-red combine ----------------
// CTA 128(slots) x 128(hidden); 256 thr, 8 warps 4m x 2n, warp tile 32x64;
// BK=64; 3-stage ring (32KB/stage); 2 CTAs/SM.
__global__ void __launch_bounds__(256, 2)
k_down(float* __restrict__ out) {
    int bt = blockIdx.y;
    if (bt >= g_ntiles) return;
    int e = g_tile_e[bt], m0 = g_tile_m0[bt], rows = g_tile_rows[bt];
    int n0 = blockIdx.x * 128;

    extern __shared__ uint32_t dsm[];
    uint32_t sbase = smem_u32(dsm);

    int tid = threadIdx.x, warp = tid >> 5, lane = tid & 31;
    int wm = warp & 3, wn = warp >> 2;

    const __half* wd_e = g_wdph + (size_t)e * HIDDEN * INTER;

    const __half* a_src[4]; int a_sz[4]; uint32_t a_off[4];
    const __half* b_src[4]; uint32_t b_off[4];
#pragma unroll
    for (int i = 0; i < 4; i++) {
        int c = tid + 256 * i;
        int r = c >> 3, c8 = c & 7;
        bool v = r < rows;
        a_src[i] = g_act + (size_t)(m0 + (v ? r : 0)) * INTER + c8 * 8;
        a_sz[i] = v ? 16 : 0;
        a_off[i] = (uint32_t)(r * 128 + ((c8 ^ (r & 7)) << 4));
        b_src[i] = wd_e + (size_t)(n0 + r) * INTER + c8 * 8;
        b_off[i] = a_off[i];
    }

    int lr = lane & 7, grp = lane >> 3;
    int rsel = (grp & 1) << 3;
    int khalf = grp >> 1;
    uint32_t a_row[2], b_row[4];
#pragma unroll
    for (int mi = 0; mi < 2; mi++)
        a_row[mi] = (uint32_t)((wm * 32 + mi * 16 + rsel + lr) * 128);
#pragma unroll
    for (int pi = 0; pi < 4; pi++)
        b_row[pi] = (uint32_t)((wn * 64 + pi * 16 + rsel + lr) * 128);

    float acc[2][8][4];
#pragma unroll
    for (int a = 0; a < 2; a++)
#pragma unroll
        for (int b = 0; b < 8; b++)
#pragma unroll
            for (int q = 0; q < 4; q++) acc[a][b][q] = 0.f;

    auto load_stage = [&](int kt, int buf) {
        uint32_t base = sbase + (uint32_t)buf * 32768u;
#pragma unroll
        for (int i = 0; i < 4; i++) {
            cp16(base + a_off[i],          a_src[i] + kt * 64, a_sz[i]);
            cp16(base + 16384u + b_off[i], b_src[i] + kt * 64, 16);
        }
    };

    load_stage(0, 0); cp_commit();
    load_stage(1, 1); cp_commit();
    load_stage(2, 2); cp_commit();

    const int KT = INTER / 64;  // 44
    for (int kt = 0; kt < KT; kt++) {
        int buf = kt % 3;
        cp_wait2();
        __syncthreads();

        uint32_t bb = sbase + (uint32_t)buf * 32768u;
#pragma unroll
        for (int s = 0; s < 4; s++) {
            uint32_t xw = (uint32_t)((((2 * s + khalf) ^ lr) << 4));
            uint32_t af[2][4];
#pragma unroll
            for (int mi = 0; mi < 2; mi++)
                ldsm_x4(af[mi], bb + a_row[mi] + xw);

            uint32_t bf[8][2];
#pragma unroll
            for (int pi = 0; pi < 4; pi++) {
                uint32_t t4[4];
                ldsm_x4(t4, bb + 16384u + b_row[pi] + xw);
                bf[2*pi][0] = t4[0]; bf[2*pi+1][0] = t4[1];
                bf[2*pi][1] = t4[2]; bf[2*pi+1][1] = t4[3];
            }
#pragma unroll
            for (int mi = 0; mi < 2; mi++)
#pragma unroll
                for (int ni = 0; ni < 8; ni++)
                    mma_f16(acc[mi][ni], af[mi], bf[ni]);
        }
        __syncthreads();
        if (kt + 3 < KT) load_stage(kt + 3, buf);
        cp_commit();
    }

    // epilogue: weighted vector scatter-add into out (one RED.64 per pair)
#pragma unroll
    for (int mi = 0; mi < 2; mi++) {
        int r_lo = wm * 32 + mi * 16 + (lane >> 2);
#pragma unroll
        for (int half = 0; half < 2; half++) {
            int row = r_lo + half * 8;
            if (row >= rows) continue;
            int tok = g_row_token[m0 + row];
            float w = g_row_w[m0 + row];
            float* orow = out + (size_t)tok * HIDDEN;
#pragma unroll
            for (int ni = 0; ni < 8; ni++) {
                int coln = n0 + wn * 64 + ni * 8 + (lane & 3) * 2;
                red_add_v2(&orow[coln],
                           w * acc[mi][ni][half * 2 + 0],
                           w * acc[mi][ni][half * 2 + 1]);
            }
        }
    }
}

// ---------------- launch ----------------
extern "C" void kernel_launch(void* const* d_in, const int* in_sizes, int n_in,
                              void* d_out, int out_size) {
    const float* x   = (const float*)d_in[0];
    const float* wg  = (const float*)d_in[1];
    const float* wgp = (const float*)d_in[2];
    const float* wup = (const float*)d_in[3];
    const float* wdp = (const float*)d_in[4];
    float* out = (float*)d_out;

    const int SMEM_DYN = 3 * 32768;  // 98304 B per CTA, 2 CTAs/SM
    cudaFuncSetAttribute(k_gateup, cudaFuncAttributeMaxDynamicSharedMemorySize, SMEM_DYN);
    cudaFuncSetAttribute(k_down,   cudaFuncAttributeMaxDynamicSharedMemorySize, SMEM_DYN);

    // zero expert counters without a kernel launch
    void* cnt_addr = nullptr;
    cudaGetSymbolAddress(&cnt_addr, g_cnt);
    cudaMemsetAsync(cnt_addr, 0, NEXP * sizeof(int));

    k_routecvt<<<ROUTE_BLOCKS + CVT_BLOCKS, 256>>>(x, wg, wgp, wup, wdp);
    k_plan<<<1, 1>>>();
    k_scatter<<<TOKENS / 256, 256>>>();

    cudaMemsetAsync(d_out, 0, (size_t)TOKENS * HIDDEN * sizeof(float));

    k_gateup<<<dim3(INTER / 64, 136), 256, SMEM_DYN>>>();
    k_down  <<<dim3(HIDDEN / 128, 136), 256, SMEM_DYN>>>(out);
}